// round 9
// baseline (speedup 1.0000x reference)
#include <cuda_runtime.h>
#include <cstdint>

// FRIENDATTN persistent kernel: online-softmax half-tile ring, 8 CTAs/SM.
// Per friend-row n (N=16384): scores = x[n]·self[n/64] (L=50,D=128),
// w = softmax(scores); out[n] = sum_l w[l]*mask[n,l]*x[n,l,:].
//
// R8 (70.1us, DRAM 78.8%): single-buffered tile leaves each CTA load-idle
// during its ~1500cyc compute phase. Here L=50 is split into 2 halves of 25
// (12.8KB); flash-style running (m, Z, acc) lets half h be REFILLED with the
// next row's half h right after this row's pooling over it -> each CTA keeps
// ~12.8KB in flight nearly always. smem ~27KB, still 8 CTAs/SM.

#define D_DIM 128
#define L_HALF 25
#define TPB   128
#define NROWS (256 * 64)
#define GRID  1216           // 152 SMs * 8 CTAs/SM

#define HALF_FLOATS (L_HALF * D_DIM)      // 3200
#define HALF_BYTES  (HALF_FLOATS * 4)     // 12800
#define SELF_BYTES  (D_DIM * 4)           // 512

// dynamic SMEM layout (float index):
//  sx     [2][3200]  @ 0        half tiles
//  sself  [2][128]   @ 6400     row-parity double buffer
//  ssc    [2][32]    @ 6656     raw scores per half
//  sw     [2][32]    @ 6720     unnormalized masked weights per half
//  sscale           @ 6784     exp(m_old - m_new)
//  sinvZ            @ 6785     1/Z after half 1
//  mbar   [2] u64    @ 6786(pad to 8B: 6788)
#define OFF_SELF   6400
#define OFF_SSC    6656
#define OFF_SW     6720
#define OFF_SCALE  6784
#define OFF_INVZ   6785
#define OFF_MBAR   6788
#define SM_FLOATS  6792      // 27168 bytes

__device__ __forceinline__ unsigned int smem_u32(const void* p)
{
    return (unsigned int)__cvta_generic_to_shared(p);
}
__device__ __forceinline__ void mbar_init(unsigned int mbar, unsigned int count)
{
    asm volatile("mbarrier.init.shared.b64 [%0], %1;" :: "r"(mbar), "r"(count) : "memory");
}
__device__ __forceinline__ void mbar_expect_tx(unsigned int mbar, unsigned int bytes)
{
    asm volatile("mbarrier.arrive.expect_tx.shared.b64 _, [%0], %1;"
                 :: "r"(mbar), "r"(bytes) : "memory");
}
__device__ __forceinline__ void mbar_wait(unsigned int mbar, unsigned int phase)
{
    asm volatile(
        "{\n\t"
        ".reg .pred P;\n\t"
        "W%=:\n\t"
        "mbarrier.try_wait.parity.acquire.cta.shared::cta.b64 P, [%0], %1, 0x989680;\n\t"
        "@!P bra W%=;\n\t"
        "}"
        :: "r"(mbar), "r"(phase) : "memory");
}
__device__ __forceinline__ void bulk_g2s(unsigned int dst, const void* src,
                                         unsigned int bytes, unsigned int mbar)
{
    asm volatile(
        "cp.async.bulk.shared::cta.global.mbarrier::complete_tx::bytes [%0], [%1], %2, [%3];"
        :: "r"(dst), "l"(src), "r"(bytes), "r"(mbar) : "memory");
}

__global__ __launch_bounds__(TPB) void friendattn_kernel(
    const float* __restrict__ x,        // [N, L, D]
    const float* __restrict__ self_x,   // [B, D]
    const void*  __restrict__ mask,     // [N, L]; dtype detected inline
    float* __restrict__ out)            // [N, D]
{
    extern __shared__ float smem[];
    const int tid  = threadIdx.x;
    const int lane = tid & 31;
    const int warp = tid >> 5;

    const unsigned int mbar0 = smem_u32(smem + OFF_MBAR);
    const unsigned int mbar1 = mbar0 + 8;

    // ---- inline mask dtype detection (first 2048 int32 words = 8KB, L2-hot) ----
    int gt1 = 0, odd_nz = 0, even_nz = 0;
    {
        const int* mw = (const int*)mask;
        #pragma unroll
        for (int it2 = 0; it2 < 16; ++it2) {
            int i = it2 * TPB + tid;
            unsigned int v = (unsigned int)mw[i];
            if (v > 1u) gt1 = 1;
            if (v != 0u) { if (i & 1) odd_nz = 1; else even_nz = 1; }
        }
    }
    const int any_gt1  = __syncthreads_or(gt1);
    const int any_odd  = __syncthreads_or(odd_nz);
    const int any_even = __syncthreads_or(even_nz);
    const int mode = any_gt1 ? 0 : ((!any_odd && any_even) ? 2 : 1);

    if (tid == 0) {
        mbar_init(mbar0, 1);
        mbar_init(mbar1, 1);
        asm volatile("fence.proxy.async.shared::cta;" ::: "memory");
    }
    __syncthreads();

    // half h of row r lives at x + r*6400 + h*3200
    // self for row-iteration k lives in sself slot (k&1)
    auto prefetch_half0 = [&](int row, int selfslot) {
        mbar_expect_tx(mbar0, HALF_BYTES + SELF_BYTES);
        bulk_g2s(smem_u32(smem), x + (size_t)row * 6400, HALF_BYTES, mbar0);
        bulk_g2s(smem_u32(smem + OFF_SELF + selfslot * D_DIM),
                 self_x + (size_t)(row >> 6) * D_DIM, SELF_BYTES, mbar0);
    };
    auto prefetch_half1 = [&](int row) {
        mbar_expect_tx(mbar1, HALF_BYTES);
        bulk_g2s(smem_u32(smem + HALF_FLOATS), x + (size_t)row * 6400 + HALF_FLOATS,
                 HALF_BYTES, mbar1);
    };

    int row = blockIdx.x;
    int it  = 0;
    if (tid == 0 && row < NROWS) { prefetch_half0(row, 0); prefetch_half1(row); }

    float* ssc = smem + OFF_SSC;
    float* sw  = smem + OFF_SW;

    while (row < NROWS) {
        const unsigned int ph = (unsigned int)(it & 1);
        const float* sself = smem + OFF_SELF + (it & 1) * D_DIM;
        float acc = 0.0f;
        float m = -3.0e38f, Z = 0.0f;   // live in warp 0 only

        #pragma unroll
        for (int h = 0; h < 2; ++h) {
            const float* sxh = smem + h * HALF_FLOATS;

            // ---- warp0: early mask load for this half ----
            float fm = 0.0f;
            if (warp == 0 && lane < L_HALF) {
                const long long mi = (long long)row * 50 + h * L_HALF + lane;
                if (mode == 0)      fm = ((const unsigned char*)mask)[mi] ? 1.0f : 0.0f;
                else if (mode == 1) fm = ((const int*)mask)[mi] ? 1.0f : 0.0f;
                else                fm = ((const int*)mask)[2 * mi] ? 1.0f : 0.0f;
            }

            // ---- wait for this half's TMA ----
            mbar_wait(h ? mbar1 : mbar0, ph);

            // ---- scores: warp w handles l = w, w+4, ... < 25 ----
            const float4 s4 = ((const float4*)sself)[lane];
            for (int l = warp; l < L_HALF; l += 4) {
                float4 v = ((const float4*)(sxh + l * D_DIM))[lane];
                float p = v.x * s4.x + v.y * s4.y + v.z * s4.z + v.w * s4.w;
                #pragma unroll
                for (int o = 16; o > 0; o >>= 1) p += __shfl_xor_sync(0xffffffffu, p, o);
                if (lane == 0) ssc[h * 32 + l] = p;
            }
            __syncthreads();

            // ---- warp0: online softmax partial update ----
            if (warp == 0) {
                float s = (lane < L_HALF) ? ssc[h * 32 + lane] : -3.0e38f;
                float hm = s;
                #pragma unroll
                for (int o = 16; o > 0; o >>= 1) hm = fmaxf(hm, __shfl_xor_sync(0xffffffffu, hm, o));
                float m_new = fmaxf(m, hm);
                float scale = __expf(m - m_new);           // 0 on first half (m=-inf)
                float e = (lane < L_HALF) ? __expf(s - m_new) : 0.0f;
                float es = e;
                #pragma unroll
                for (int o = 16; o > 0; o >>= 1) es += __shfl_xor_sync(0xffffffffu, es, o);
                Z = Z * scale + es;
                m = m_new;
                if (lane < L_HALF) sw[h * 32 + lane] = e * fm;
                if (lane == 0) {
                    smem[OFF_SCALE] = scale;
                    if (h == 1) smem[OFF_INVZ] = 1.0f / Z;
                }
            }
            __syncthreads();

            // ---- pooling over this half (rescale then accumulate) ----
            acc *= smem[OFF_SCALE];
            #pragma unroll
            for (int l = 0; l < L_HALF; ++l)
                acc = fmaf(sw[h * 32 + l], sxh[l * D_DIM + tid], acc);
            __syncthreads();   // half h fully consumed

            // ---- refill half h with next row's half h ----
            if (tid == 0) {
                const int nr = row + GRID;
                if (nr < NROWS) {
                    if (h == 0) prefetch_half0(nr, (it + 1) & 1);
                    else        prefetch_half1(nr);
                }
            }
        }

        out[(size_t)row * D_DIM + tid] = acc * smem[OFF_INVZ];

        row += GRID;
        ++it;
    }
}

extern "C" void kernel_launch(void* const* d_in, const int* in_sizes, int n_in,
                              void* d_out, int out_size)
{
    const float* x      = (const float*)d_in[0];
    const float* self_x = (const float*)d_in[1];
    const void*  mask   = d_in[n_in - 1];
    float* out = (float*)d_out;

    cudaFuncSetAttribute(friendattn_kernel,
                         cudaFuncAttributeMaxDynamicSharedMemorySize,
                         SM_FLOATS * sizeof(float));

    friendattn_kernel<<<GRID, TPB, SM_FLOATS * sizeof(float)>>>(x, self_x, mask, out);
}

// round 10
// speedup vs baseline: 1.0547x; 1.0547x over previous
#include <cuda_runtime.h>
#include <cstdint>

// FRIENDATTN persistent kernel: R8 structure + split-tile overlap, 8 CTAs/SM.
// Per friend-row n (N=16384): scores = x[n]·self[n/64] (L=50,D=128),
// w = softmax(scores); out[n] = sum_l w[l]*mask[n,l]*x[n,l,:].
//
// R8 (70.1us, DRAM 78.8%): zero bytes in flight per CTA during compute.
// R9's online-softmax overlap regressed (issue-side overhead). This version
// keeps R8's cheap single softmax and adds overlap only via two mbarriers:
// half h of the NEXT row is refilled as soon as pooling over half h is done.
// Extra cost vs R8: one barrier + one mbar wait.

#define D_DIM 128
#define L_DIM 50
#define L_HALF 25
#define TPB   128
#define NROWS (256 * 64)
#define GRID  1216           // 152 SMs * 8 CTAs/SM

#define TILE_FLOATS (L_DIM * D_DIM)       // 6400
#define HALF_FLOATS (L_HALF * D_DIM)      // 3200
#define HALF_BYTES  (HALF_FLOATS * 4)     // 12800
#define SELF_BYTES  (D_DIM * 4)           // 512

// dynamic SMEM layout (float index):
//  sx     [6400]  @ 0        (half0 @0, half1 @3200)
//  sself  [128]   @ 6400
//  sscore [64]    @ 6528
//  sw     [64]    @ 6592
//  mbar   [2]u64  @ 6656
#define OFF_SELF   6400
#define OFF_SCORE  6528
#define OFF_W      6592
#define OFF_MBAR   6656
#define SM_FLOATS  6660      // 26640 bytes

__device__ __forceinline__ unsigned int smem_u32(const void* p)
{
    return (unsigned int)__cvta_generic_to_shared(p);
}
__device__ __forceinline__ void mbar_init(unsigned int mbar, unsigned int count)
{
    asm volatile("mbarrier.init.shared.b64 [%0], %1;" :: "r"(mbar), "r"(count) : "memory");
}
__device__ __forceinline__ void mbar_expect_tx(unsigned int mbar, unsigned int bytes)
{
    asm volatile("mbarrier.arrive.expect_tx.shared.b64 _, [%0], %1;"
                 :: "r"(mbar), "r"(bytes) : "memory");
}
__device__ __forceinline__ void mbar_wait(unsigned int mbar, unsigned int phase)
{
    asm volatile(
        "{\n\t"
        ".reg .pred P;\n\t"
        "W%=:\n\t"
        "mbarrier.try_wait.parity.acquire.cta.shared::cta.b64 P, [%0], %1, 0x989680;\n\t"
        "@!P bra W%=;\n\t"
        "}"
        :: "r"(mbar), "r"(phase) : "memory");
}
__device__ __forceinline__ void bulk_g2s(unsigned int dst, const void* src,
                                         unsigned int bytes, unsigned int mbar)
{
    asm volatile(
        "cp.async.bulk.shared::cta.global.mbarrier::complete_tx::bytes [%0], [%1], %2, [%3];"
        :: "r"(dst), "l"(src), "r"(bytes), "r"(mbar) : "memory");
}

__global__ __launch_bounds__(TPB) void friendattn_kernel(
    const float* __restrict__ x,        // [N, L, D]
    const float* __restrict__ self_x,   // [B, D]
    const void*  __restrict__ mask,     // [N, L]; dtype detected inline
    float* __restrict__ out)            // [N, D]
{
    extern __shared__ float smem[];
    const int tid  = threadIdx.x;
    const int lane = tid & 31;
    const int warp = tid >> 5;

    const unsigned int mbar0 = smem_u32(smem + OFF_MBAR);
    const unsigned int mbar1 = mbar0 + 8;

    // ---- inline mask dtype detection (first 2048 int32 words = 8KB, L2-hot) ----
    int gt1 = 0, odd_nz = 0, even_nz = 0;
    {
        const int* mw = (const int*)mask;
        #pragma unroll
        for (int it2 = 0; it2 < 16; ++it2) {
            int i = it2 * TPB + tid;
            unsigned int v = (unsigned int)mw[i];
            if (v > 1u) gt1 = 1;
            if (v != 0u) { if (i & 1) odd_nz = 1; else even_nz = 1; }
        }
    }
    const int any_gt1  = __syncthreads_or(gt1);
    const int any_odd  = __syncthreads_or(odd_nz);
    const int any_even = __syncthreads_or(even_nz);
    const int mode = any_gt1 ? 0 : ((!any_odd && any_even) ? 2 : 1);

    if (tid == 0) {
        mbar_init(mbar0, 1);
        mbar_init(mbar1, 1);
        asm volatile("fence.proxy.async.shared::cta;" ::: "memory");
    }
    __syncthreads();

    // half0 = l 0..24 (+self on mbar0), half1 = l 25..49 (mbar1)
    auto prefetch_half0 = [&](int row) {
        mbar_expect_tx(mbar0, HALF_BYTES + SELF_BYTES);
        bulk_g2s(smem_u32(smem), x + (size_t)row * TILE_FLOATS, HALF_BYTES, mbar0);
        bulk_g2s(smem_u32(smem + OFF_SELF),
                 self_x + (size_t)(row >> 6) * D_DIM, SELF_BYTES, mbar0);
    };
    auto prefetch_half1 = [&](int row) {
        mbar_expect_tx(mbar1, HALF_BYTES);
        bulk_g2s(smem_u32(smem + HALF_FLOATS),
                 x + (size_t)row * TILE_FLOATS + HALF_FLOATS, HALF_BYTES, mbar1);
    };

    int row = blockIdx.x;
    if (tid == 0 && row < NROWS) { prefetch_half0(row); prefetch_half1(row); }

    unsigned int phase = 0u;
    float* sscore = smem + OFF_SCORE;
    float* sw     = smem + OFF_W;

    while (row < NROWS) {
        // ---- softmax warp issues mask loads early (overlap with wait) ----
        float fm0 = 0.0f, fm1 = 0.0f;
        if (warp == 0) {
            const long long mbase = (long long)row * L_DIM;
            if (mode == 0) {
                const unsigned char* m = (const unsigned char*)mask + mbase;
                fm0 = m[lane] ? 1.0f : 0.0f;
                if (lane + 32 < L_DIM) fm1 = m[lane + 32] ? 1.0f : 0.0f;
            } else if (mode == 1) {
                const int* m = (const int*)mask + mbase;
                fm0 = m[lane] ? 1.0f : 0.0f;
                if (lane + 32 < L_DIM) fm1 = m[lane + 32] ? 1.0f : 0.0f;
            } else {
                const int* m = (const int*)mask + 2 * mbase;
                fm0 = m[2 * lane] ? 1.0f : 0.0f;
                if (lane + 32 < L_DIM) fm1 = m[2 * (lane + 32)] ? 1.0f : 0.0f;
            }
        }

        const float* sx = smem;
        const float4 s4v = ((const float4*)(smem + OFF_SELF))[lane];

        // ---- scores half0 as soon as it lands ----
        mbar_wait(mbar0, phase);
        // re-read self AFTER mbar0 arrival (carried in same tx group)
        const float4 s4 = ((const float4*)(smem + OFF_SELF))[lane];
        (void)s4v;
        for (int l = warp; l < L_HALF; l += 4) {
            float4 v = ((const float4*)(sx + l * D_DIM))[lane];
            float p = v.x * s4.x + v.y * s4.y + v.z * s4.z + v.w * s4.w;
            #pragma unroll
            for (int o = 16; o > 0; o >>= 1) p += __shfl_xor_sync(0xffffffffu, p, o);
            if (lane == 0) sscore[l] = p;
        }

        // ---- scores half1 ----
        mbar_wait(mbar1, phase);
        for (int l = L_HALF + warp; l < L_DIM; l += 4) {
            float4 v = ((const float4*)(sx + l * D_DIM))[lane];
            float p = v.x * s4.x + v.y * s4.y + v.z * s4.z + v.w * s4.w;
            #pragma unroll
            for (int o = 16; o > 0; o >>= 1) p += __shfl_xor_sync(0xffffffffu, p, o);
            if (lane == 0) sscore[l] = p;
        }
        phase ^= 1u;
        __syncthreads();

        // ---- softmax over L=50, mask folded in (warp 0) ----
        if (warp == 0) {
            float v0 = sscore[lane];
            float v1 = (lane + 32 < L_DIM) ? sscore[lane + 32] : -3.0e38f;
            float mx = fmaxf(v0, v1);
            #pragma unroll
            for (int o = 16; o > 0; o >>= 1) mx = fmaxf(mx, __shfl_xor_sync(0xffffffffu, mx, o));
            float e0 = __expf(v0 - mx);
            float e1 = (lane + 32 < L_DIM) ? __expf(v1 - mx) : 0.0f;
            float sum = e0 + e1;
            #pragma unroll
            for (int o = 16; o > 0; o >>= 1) sum += __shfl_xor_sync(0xffffffffu, sum, o);
            float inv = 1.0f / sum;
            sw[lane] = e0 * inv * fm0;
            if (lane + 32 < L_DIM) sw[lane + 32] = e1 * inv * fm1;
        }
        __syncthreads();

        const int nr = row + GRID;

        // ---- pooling half0, then refill half0 with next row ----
        float acc = 0.0f;
        #pragma unroll
        for (int l = 0; l < L_HALF; ++l)
            acc = fmaf(sw[l], sx[l * D_DIM + tid], acc);
        __syncthreads();                         // half0 + sself fully consumed
        if (tid == 0 && nr < NROWS) prefetch_half0(nr);

        // ---- pooling half1, then refill half1 ----
        #pragma unroll
        for (int l = L_HALF; l < L_DIM; ++l)
            acc = fmaf(sw[l], sx[l * D_DIM + tid], acc);
        out[(size_t)row * D_DIM + tid] = acc;
        __syncthreads();                         // half1 + sw fully consumed
        if (tid == 0 && nr < NROWS) prefetch_half1(nr);

        row = nr;
    }
}

extern "C" void kernel_launch(void* const* d_in, const int* in_sizes, int n_in,
                              void* d_out, int out_size)
{
    const float* x      = (const float*)d_in[0];
    const float* self_x = (const float*)d_in[1];
    const void*  mask   = d_in[n_in - 1];
    float* out = (float*)d_out;

    cudaFuncSetAttribute(friendattn_kernel,
                         cudaFuncAttributeMaxDynamicSharedMemorySize,
                         SM_FLOATS * sizeof(float));

    friendattn_kernel<<<GRID, TPB, SM_FLOATS * sizeof(float)>>>(x, self_x, mask, out);
}